// round 7
// baseline (speedup 1.0000x reference)
#include <cuda_runtime.h>
#include <cstdint>

typedef unsigned long long u64;

// ---------------- f32x2 packed-fp32 helpers (Blackwell FFMA2 path) -----------
__device__ __forceinline__ u64 ffma2(u64 a, u64 b, u64 c) {
    u64 d;
    asm("fma.rn.f32x2 %0, %1, %2, %3;" : "=l"(d) : "l"(a), "l"(b), "l"(c));
    return d;
}
__device__ __forceinline__ u64 pack2(float lo, float hi) {
    u64 r;
    asm("mov.b64 %0, {%1, %2};" : "=l"(r) : "f"(lo), "f"(hi));
    return r;
}
__device__ __forceinline__ float2 unpack2(u64 v) {
    float2 f;
    asm("mov.b64 {%0, %1}, %2;" : "=f"(f.x), "=f"(f.y) : "l"(v));
    return f;
}
__device__ __forceinline__ uint32_t smem_u32(const void* p) {
    uint32_t a;
    asm("{ .reg .u64 t; cvta.to.shared.u64 t, %1; cvt.u32.u64 %0, t; }"
        : "=r"(a) : "l"(p));
    return a;
}

// =============================================================================
// Phase 1: x_proj GEMM.  out[row, j] = bias[j] + sum_k X[row,k] * W[j,k]
// X: [131072, 256], W row stride 512 (W_x = first 256 cols), out: [131072, 256]
// 128x128 tile, BK=16, 256 threads, 8x8 microtile, f32x2 accumulators.
// =============================================================================
__global__ __launch_bounds__(256, 2) void xproj_gemm(
    const float* __restrict__ X, const float* __restrict__ W,
    const float* __restrict__ bias, float* __restrict__ out)
{
    __shared__ float As[2][16][128];
    __shared__ float Bs[2][16][128];

    const int tid   = threadIdx.x;
    const int mBase = blockIdx.x * 128;
    const int nBase = blockIdx.y * 128;

    const int lrow = tid & 127;
    const int lkg0 = tid >> 7;              // 0 or 1

    const float* Aptr = X + (size_t)(mBase + lrow) * 256;
    const float* Bptr = W + (size_t)(nBase + lrow) * 512;

    const int tx = tid & 15;
    const int ty = tid >> 4;
    const int j0 = tx * 8;
    const int r0 = ty * 8;

    u64 acc[4][8];
    #pragma unroll
    for (int ri = 0; ri < 4; ri++)
        #pragma unroll
        for (int j = 0; j < 8; j++) acc[ri][j] = 0ull;

    // ---- prologue: load k-tile 0 into buffer 0 ----
    {
        float4 av0 = *(const float4*)(Aptr + lkg0 * 4);
        float4 av1 = *(const float4*)(Aptr + (lkg0 + 2) * 4);
        float4 bv0 = *(const float4*)(Bptr + lkg0 * 4);
        float4 bv1 = *(const float4*)(Bptr + (lkg0 + 2) * 4);
        const int ka = lkg0 * 4, kb = (lkg0 + 2) * 4;
        As[0][ka+0][lrow] = av0.x; As[0][ka+1][lrow] = av0.y;
        As[0][ka+2][lrow] = av0.z; As[0][ka+3][lrow] = av0.w;
        As[0][kb+0][lrow] = av1.x; As[0][kb+1][lrow] = av1.y;
        As[0][kb+2][lrow] = av1.z; As[0][kb+3][lrow] = av1.w;
        Bs[0][ka+0][lrow] = bv0.x; Bs[0][ka+1][lrow] = bv0.y;
        Bs[0][ka+2][lrow] = bv0.z; Bs[0][ka+3][lrow] = bv0.w;
        Bs[0][kb+0][lrow] = bv1.x; Bs[0][kb+1][lrow] = bv1.y;
        Bs[0][kb+2][lrow] = bv1.z; Bs[0][kb+3][lrow] = bv1.w;
    }
    __syncthreads();

    #pragma unroll 1
    for (int kt = 0; kt < 16; kt++) {
        const int cur = kt & 1;
        float4 na0, na1, nb0, nb1;
        if (kt < 15) {
            const float* ap = Aptr + (kt + 1) * 16;
            const float* bp = Bptr + (kt + 1) * 16;
            na0 = *(const float4*)(ap + lkg0 * 4);
            na1 = *(const float4*)(ap + (lkg0 + 2) * 4);
            nb0 = *(const float4*)(bp + lkg0 * 4);
            nb1 = *(const float4*)(bp + (lkg0 + 2) * 4);
        }
        #pragma unroll
        for (int k = 0; k < 16; k++) {
            float4 a0 = *(const float4*)&As[cur][k][r0];
            float4 a1 = *(const float4*)&As[cur][k][r0 + 4];
            float4 b0 = *(const float4*)&Bs[cur][k][j0];
            float4 b1 = *(const float4*)&Bs[cur][k][j0 + 4];
            u64 aa[4];
            aa[0] = pack2(a0.x, a0.y); aa[1] = pack2(a0.z, a0.w);
            aa[2] = pack2(a1.x, a1.y); aa[3] = pack2(a1.z, a1.w);
            float bsv[8] = {b0.x, b0.y, b0.z, b0.w, b1.x, b1.y, b1.z, b1.w};
            #pragma unroll
            for (int j = 0; j < 8; j++) {
                u64 bb = pack2(bsv[j], bsv[j]);
                #pragma unroll
                for (int ri = 0; ri < 4; ri++)
                    acc[ri][j] = ffma2(aa[ri], bb, acc[ri][j]);
            }
        }
        if (kt < 15) {
            const int nxt = cur ^ 1;
            const int ka = lkg0 * 4, kb = (lkg0 + 2) * 4;
            As[nxt][ka+0][lrow] = na0.x; As[nxt][ka+1][lrow] = na0.y;
            As[nxt][ka+2][lrow] = na0.z; As[nxt][ka+3][lrow] = na0.w;
            As[nxt][kb+0][lrow] = na1.x; As[nxt][kb+1][lrow] = na1.y;
            As[nxt][kb+2][lrow] = na1.z; As[nxt][kb+3][lrow] = na1.w;
            Bs[nxt][ka+0][lrow] = nb0.x; Bs[nxt][ka+1][lrow] = nb0.y;
            Bs[nxt][ka+2][lrow] = nb0.z; Bs[nxt][ka+3][lrow] = nb0.w;
            Bs[nxt][kb+0][lrow] = nb1.x; Bs[nxt][kb+1][lrow] = nb1.y;
            Bs[nxt][kb+2][lrow] = nb1.z; Bs[nxt][kb+3][lrow] = nb1.w;
        }
        __syncthreads();
    }

    // ---- epilogue: add bias, store ----
    float bvv[8];
    *(float4*)&bvv[0] = *(const float4*)(bias + nBase + j0);
    *(float4*)&bvv[4] = *(const float4*)(bias + nBase + j0 + 4);
    #pragma unroll
    for (int ri = 0; ri < 4; ri++) {
        float lo[8], hi[8];
        #pragma unroll
        for (int j = 0; j < 8; j++) {
            float2 f = unpack2(acc[ri][j]);
            lo[j] = f.x + bvv[j];
            hi[j] = f.y + bvv[j];
        }
        float* orow0 = out + (size_t)(mBase + r0 + 2 * ri) * 256 + nBase + j0;
        float* orow1 = orow0 + 256;
        *(float4*)(orow0)     = make_float4(lo[0], lo[1], lo[2], lo[3]);
        *(float4*)(orow0 + 4) = make_float4(lo[4], lo[5], lo[6], lo[7]);
        *(float4*)(orow1)     = make_float4(hi[0], hi[1], hi[2], hi[3]);
        *(float4*)(orow1 + 4) = make_float4(hi[4], hi[5], hi[6], hi[7]);
    }
}

// =============================================================================
// Phase 2: recurrence on a 2-CTA CLUSTER per batch.  128 CTAs total.
//   out[b,t,:] = xproj[b,t,:] + W_h @ h_prev      (in place: out holds xproj)
// Each CTA owns 128 of the 256 outputs -> weights per thread = 32 u64 pairs
// = 64 regs: ALL of W_h is register-resident, no SMEM weight streaming.
// Thread (jl = tid>>2, q = tid&3): output j = rank*128+jl, k-chunk q*64..+63.
// h (full 256 values) kept in both CTAs' SMEM, double-buffered, laid out as
// 4 chunks of 32 pairs with stride 34 (bank-conflict-free LDS.128 broadcast).
// After computing its 128 new h values, each CTA stores them into BOTH its
// own and the peer's next-step buffer (mapa + st.shared::cluster), then a
// cluster barrier (release/acquire) publishes them for the next step.
// =============================================================================
__global__ __launch_bounds__(512, 1) __cluster_dims__(2, 1, 1)
void rnn_scan2(const float* __restrict__ W, const float* __restrict__ hidden,
               float* __restrict__ out)
{
    __shared__ u64 h2[2][136];   // [buffer][4 chunks * 34 pairs]

    const int tid = threadIdx.x;
    uint32_t rank;
    asm("mov.u32 %0, %%cluster_ctarank;" : "=r"(rank));
    const int b  = blockIdx.x >> 1;
    const int q  = tid & 3;
    const int jl = tid >> 2;
    const int j  = (int)rank * 128 + jl;

    // ---- weights: 32 pairs, fully in registers ----
    u64 w[32];
    const u64* wr = (const u64*)(W + (size_t)j * 512 + 256) + q * 32;
    #pragma unroll
    for (int i = 0; i < 32; i++) w[i] = wr[i];

    // ---- init h buffer 0 (each CTA holds the FULL 256-vector) ----
    if (tid < 128) {
        u64 hv = ((const u64*)(hidden + (size_t)b * 256))[tid];
        h2[0][(tid >> 5) * 34 + (tid & 31)] = hv;
    }

    // ---- writer setup: q==0 lanes own output j ----
    const bool writer = (q == 0);
    float* outp = out + (size_t)b * 2048 * 256 + j;
    float  xpre = 0.f;
    if (writer) xpre = *outp;                       // xproj[b,0,j]

    // h-slot (float index) for this writer's element in a buffer
    const int p    = j >> 1;
    const int slot = ((p >> 5) * 34 + (p & 31)) * 2 + (j & 1);
    uint32_t loc0 = smem_u32(&((float*)h2[0])[slot]);
    uint32_t loc1 = smem_u32(&((float*)h2[1])[slot]);
    uint32_t rem0, rem1;
    {
        uint32_t peer = rank ^ 1u;
        asm("mapa.shared::cluster.u32 %0, %1, %2;" : "=r"(rem0) : "r"(loc0), "r"(peer));
        asm("mapa.shared::cluster.u32 %0, %1, %2;" : "=r"(rem1) : "r"(loc1), "r"(peer));
    }

    __syncthreads();

    #pragma unroll 1
    for (int t = 0; t < 2048; t++) {
        const u64* hb = h2[t & 1] + q * 34;
        u64 a0 = 0, a1 = 0;
        #pragma unroll
        for (int i = 0; i < 16; i++) {
            ulonglong2 hh = *(const ulonglong2*)(hb + 2 * i);
            a0 = ffma2(w[2 * i],     hh.x, a0);
            a1 = ffma2(w[2 * i + 1], hh.y, a1);
        }
        float2 f0 = unpack2(a0), f1 = unpack2(a1);
        float s = (f0.x + f0.y) + (f1.x + f1.y);
        // reduce the 4 q-partials (lanes 4a..4a+3 hold the same output j)
        s += __shfl_xor_sync(0xffffffffu, s, 1);
        s += __shfl_xor_sync(0xffffffffu, s, 2);

        if (writer) {
            float hnew = s + xpre;
            uint32_t la = (t & 1) ? loc0 : loc1;    // write buffer (t+1)&1
            uint32_t ra = (t & 1) ? rem0 : rem1;
            asm volatile("st.shared.f32 [%0], %1;" :: "r"(la), "f"(hnew) : "memory");
            asm volatile("st.shared::cluster.f32 [%0], %1;" :: "r"(ra), "f"(hnew) : "memory");
            *outp = hnew;
            if (t < 2047) xpre = outp[256];         // prefetch next xproj
            outp += 256;
        }
        // cluster barrier: releases our DSMEM stores, acquires peer's
        asm volatile("barrier.cluster.arrive.aligned;" ::: "memory");
        asm volatile("barrier.cluster.wait.aligned;"   ::: "memory");
    }
}

// =============================================================================
extern "C" void kernel_launch(void* const* d_in, const int* in_sizes, int n_in,
                              void* d_out, int out_size)
{
    (void)in_sizes; (void)n_in; (void)out_size;
    const float* X      = (const float*)d_in[0];   // input_seq [64,2048,256]
    const float* hidden = (const float*)d_in[1];   // [64,256]
    const float* W      = (const float*)d_in[2];   // [256,512]
    const float* bias   = (const float*)d_in[3];   // [256]
    float* out          = (float*)d_out;           // [64,2048,256]

    // Phase 1: x_proj into d_out (scratch-in-place).
    dim3 g1(1024, 2);
    xproj_gemm<<<g1, 256>>>(X, W, bias, out);

    // Phase 2: 128 CTAs as 64 clusters of 2 (one cluster per batch).
    cudaLaunchConfig_t cfg = {};
    cfg.gridDim  = dim3(128, 1, 1);
    cfg.blockDim = dim3(512, 1, 1);
    cfg.dynamicSmemBytes = 0;
    cudaLaunchAttribute attrs[1];
    attrs[0].id = cudaLaunchAttributeClusterDimension;
    attrs[0].val.clusterDim.x = 2;
    attrs[0].val.clusterDim.y = 1;
    attrs[0].val.clusterDim.z = 1;
    cfg.attrs = attrs;
    cfg.numAttrs = 1;
    cudaLaunchKernelEx(&cfg, rnn_scan2, W, hidden, out);
}

// round 8
// speedup vs baseline: 1.6420x; 1.6420x over previous
#include <cuda_runtime.h>
#include <cstdint>

typedef unsigned long long u64;

// 256x256 fp32 scratch for W_h @ W_h  (device-global: allocation-free scratch)
__device__ float g_W2[256 * 256];

// ---------------- f32x2 packed-fp32 helpers (Blackwell FFMA2 path) -----------
__device__ __forceinline__ u64 ffma2(u64 a, u64 b, u64 c) {
    u64 d;
    asm("fma.rn.f32x2 %0, %1, %2, %3;" : "=l"(d) : "l"(a), "l"(b), "l"(c));
    return d;
}
__device__ __forceinline__ u64 pack2(float lo, float hi) {
    u64 r;
    asm("mov.b64 %0, {%1, %2};" : "=l"(r) : "f"(lo), "f"(hi));
    return r;
}
__device__ __forceinline__ float2 unpack2(u64 v) {
    float2 f;
    asm("mov.b64 {%0, %1}, %2;" : "=f"(f.x), "=f"(f.y) : "l"(v));
    return f;
}

// =============================================================================
// GEMM mainloop core (shared by all three big GEMMs).
// As/Bs double-buffered 16x128 tiles; 256 threads; 8x8 microtile into acc.
// A row pointer is arbitrary per lrow (caller computes), B row = W-style row.
// =============================================================================
struct GemmCore {
    float (*As)[16][128];
    float (*Bs)[16][128];
};

__device__ __forceinline__ void gemm_mainloop(
    float As[2][16][128], float Bs[2][16][128],
    const float* Aptr, const float* Bptr,
    int lrow, int lkg0, int r0, int j0, u64 acc[4][8])
{
    // prologue: k-tile 0 into buffer 0
    {
        float4 av0 = *(const float4*)(Aptr + lkg0 * 4);
        float4 av1 = *(const float4*)(Aptr + (lkg0 + 2) * 4);
        float4 bv0 = *(const float4*)(Bptr + lkg0 * 4);
        float4 bv1 = *(const float4*)(Bptr + (lkg0 + 2) * 4);
        const int ka = lkg0 * 4, kb = (lkg0 + 2) * 4;
        As[0][ka+0][lrow] = av0.x; As[0][ka+1][lrow] = av0.y;
        As[0][ka+2][lrow] = av0.z; As[0][ka+3][lrow] = av0.w;
        As[0][kb+0][lrow] = av1.x; As[0][kb+1][lrow] = av1.y;
        As[0][kb+2][lrow] = av1.z; As[0][kb+3][lrow] = av1.w;
        Bs[0][ka+0][lrow] = bv0.x; Bs[0][ka+1][lrow] = bv0.y;
        Bs[0][ka+2][lrow] = bv0.z; Bs[0][ka+3][lrow] = bv0.w;
        Bs[0][kb+0][lrow] = bv1.x; Bs[0][kb+1][lrow] = bv1.y;
        Bs[0][kb+2][lrow] = bv1.z; Bs[0][kb+3][lrow] = bv1.w;
    }
    __syncthreads();

    #pragma unroll 1
    for (int kt = 0; kt < 16; kt++) {
        const int cur = kt & 1;
        float4 na0, na1, nb0, nb1;
        if (kt < 15) {
            const float* ap = Aptr + (kt + 1) * 16;
            const float* bp = Bptr + (kt + 1) * 16;
            na0 = *(const float4*)(ap + lkg0 * 4);
            na1 = *(const float4*)(ap + (lkg0 + 2) * 4);
            nb0 = *(const float4*)(bp + lkg0 * 4);
            nb1 = *(const float4*)(bp + (lkg0 + 2) * 4);
        }
        #pragma unroll
        for (int k = 0; k < 16; k++) {
            float4 a0 = *(const float4*)&As[cur][k][r0];
            float4 a1 = *(const float4*)&As[cur][k][r0 + 4];
            float4 b0 = *(const float4*)&Bs[cur][k][j0];
            float4 b1 = *(const float4*)&Bs[cur][k][j0 + 4];
            u64 aa[4];
            aa[0] = pack2(a0.x, a0.y); aa[1] = pack2(a0.z, a0.w);
            aa[2] = pack2(a1.x, a1.y); aa[3] = pack2(a1.z, a1.w);
            float bsv[8] = {b0.x, b0.y, b0.z, b0.w, b1.x, b1.y, b1.z, b1.w};
            #pragma unroll
            for (int j = 0; j < 8; j++) {
                u64 bb = pack2(bsv[j], bsv[j]);
                #pragma unroll
                for (int ri = 0; ri < 4; ri++)
                    acc[ri][j] = ffma2(aa[ri], bb, acc[ri][j]);
            }
        }
        if (kt < 15) {
            const int nxt = cur ^ 1;
            const int ka = lkg0 * 4, kb = (lkg0 + 2) * 4;
            As[nxt][ka+0][lrow] = na0.x; As[nxt][ka+1][lrow] = na0.y;
            As[nxt][ka+2][lrow] = na0.z; As[nxt][ka+3][lrow] = na0.w;
            As[nxt][kb+0][lrow] = na1.x; As[nxt][kb+1][lrow] = na1.y;
            As[nxt][kb+2][lrow] = na1.z; As[nxt][kb+3][lrow] = na1.w;
            Bs[nxt][ka+0][lrow] = nb0.x; Bs[nxt][ka+1][lrow] = nb0.y;
            Bs[nxt][ka+2][lrow] = nb0.z; Bs[nxt][ka+3][lrow] = nb0.w;
            Bs[nxt][kb+0][lrow] = nb1.x; Bs[nxt][kb+1][lrow] = nb1.y;
            Bs[nxt][kb+2][lrow] = nb1.z; Bs[nxt][kb+3][lrow] = nb1.w;
        }
        __syncthreads();
    }
}

// =============================================================================
// Phase 1: x_proj GEMM.  out[row, j] = bias[j] + sum_k X[row,k] * W_x[j,k]
// =============================================================================
__global__ __launch_bounds__(256, 2) void xproj_gemm(
    const float* __restrict__ X, const float* __restrict__ W,
    const float* __restrict__ bias, float* __restrict__ out)
{
    __shared__ float As[2][16][128];
    __shared__ float Bs[2][16][128];

    const int tid   = threadIdx.x;
    const int mBase = blockIdx.x * 128;
    const int nBase = blockIdx.y * 128;
    const int lrow  = tid & 127;
    const int lkg0  = tid >> 7;
    const int tx = tid & 15, ty = tid >> 4;
    const int j0 = tx * 8,   r0 = ty * 8;

    const float* Aptr = X + (size_t)(mBase + lrow) * 256;
    const float* Bptr = W + (size_t)(nBase + lrow) * 512;

    u64 acc[4][8];
    #pragma unroll
    for (int ri = 0; ri < 4; ri++)
        #pragma unroll
        for (int j = 0; j < 8; j++) acc[ri][j] = 0ull;

    gemm_mainloop(As, Bs, Aptr, Bptr, lrow, lkg0, r0, j0, acc);

    float bvv[8];
    *(float4*)&bvv[0] = *(const float4*)(bias + nBase + j0);
    *(float4*)&bvv[4] = *(const float4*)(bias + nBase + j0 + 4);
    #pragma unroll
    for (int ri = 0; ri < 4; ri++) {
        float lo[8], hi[8];
        #pragma unroll
        for (int j = 0; j < 8; j++) {
            float2 f = unpack2(acc[ri][j]);
            lo[j] = f.x + bvv[j];
            hi[j] = f.y + bvv[j];
        }
        float* orow0 = out + (size_t)(mBase + r0 + 2 * ri) * 256 + nBase + j0;
        float* orow1 = orow0 + 256;
        *(float4*)(orow0)     = make_float4(lo[0], lo[1], lo[2], lo[3]);
        *(float4*)(orow0 + 4) = make_float4(lo[4], lo[5], lo[6], lo[7]);
        *(float4*)(orow1)     = make_float4(hi[0], hi[1], hi[2], hi[3]);
        *(float4*)(orow1 + 4) = make_float4(hi[4], hi[5], hi[6], hi[7]);
    }
}

// =============================================================================
// W2 kernel: g_W2[j,k] = sum_m Wh[j,m] * Wh[m,k],  Wh[j,k] = W[j*512+256+k].
// 256 blocks (one per j), 256 threads (one per k).
// =============================================================================
__global__ __launch_bounds__(256) void w2_kernel(const float* __restrict__ W)
{
    __shared__ float rowj[256];
    const int j = blockIdx.x;
    const int k = threadIdx.x;
    rowj[k] = W[(size_t)j * 512 + 256 + k];
    __syncthreads();
    float acc = 0.f;
    #pragma unroll 8
    for (int m = 0; m < 256; m++)
        acc += rowj[m] * W[(size_t)m * 512 + 256 + k];
    g_W2[j * 256 + k] = acc;
}

// =============================================================================
// Corrections GEMM: for r = b*1024 + i  (65536 rows):
//   out[b, 2i+1, :] = Wh @ xp[b, 2i, :] + xp[b, 2i+1, :]
// (xp staged in out; reads even rows + odd rows, writes odd rows in place)
// =============================================================================
__global__ __launch_bounds__(256, 2) void corr_gemm(
    const float* __restrict__ W, float* __restrict__ out)
{
    __shared__ float As[2][16][128];
    __shared__ float Bs[2][16][128];

    const int tid   = threadIdx.x;
    const int mBase = blockIdx.x * 128;
    const int nBase = blockIdx.y * 128;
    const int lrow  = tid & 127;
    const int lkg0  = tid >> 7;
    const int tx = tid & 15, ty = tid >> 4;
    const int j0 = tx * 8,   r0 = ty * 8;

    const int rA = mBase + lrow;
    const int bA = rA >> 10, iA = rA & 1023;
    const float* Aptr = out + ((size_t)bA * 2048 + 2 * iA) * 256;      // xp even row
    const float* Bptr = W + (size_t)(nBase + lrow) * 512 + 256;        // Wh rows

    u64 acc[4][8];
    #pragma unroll
    for (int ri = 0; ri < 4; ri++)
        #pragma unroll
        for (int j = 0; j < 8; j++) acc[ri][j] = 0ull;

    gemm_mainloop(As, Bs, Aptr, Bptr, lrow, lkg0, r0, j0, acc);

    #pragma unroll
    for (int ri = 0; ri < 4; ri++) {
        #pragma unroll
        for (int half = 0; half < 2; half++) {
            const int rr = mBase + r0 + 2 * ri + half;
            const int b = rr >> 10, i = rr & 1023;
            float* orow = out + ((size_t)b * 2048 + 2 * i + 1) * 256 + nBase + j0;
            float4 x0 = *(const float4*)(orow);
            float4 x1 = *(const float4*)(orow + 4);
            float v[8];
            #pragma unroll
            for (int j = 0; j < 8; j++) {
                float2 f = unpack2(acc[ri][j]);
                v[j] = half ? f.y : f.x;
            }
            *(float4*)(orow)     = make_float4(v[0]+x0.x, v[1]+x0.y, v[2]+x0.z, v[3]+x0.w);
            *(float4*)(orow + 4) = make_float4(v[4]+x1.x, v[5]+x1.y, v[6]+x1.z, v[7]+x1.w);
        }
    }
}

// =============================================================================
// Backfill GEMM: for r = b*1024 + i:
//   out[b, 2i, :] = Wh @ h_prev + xp[b, 2i, :]
//   h_prev = out[b, 2i-1, :] (i>0)  or  hidden[b, :] (i==0)
// =============================================================================
__global__ __launch_bounds__(256, 2) void backfill_gemm(
    const float* __restrict__ W, const float* __restrict__ hidden,
    float* __restrict__ out)
{
    __shared__ float As[2][16][128];
    __shared__ float Bs[2][16][128];

    const int tid   = threadIdx.x;
    const int mBase = blockIdx.x * 128;
    const int nBase = blockIdx.y * 128;
    const int lrow  = tid & 127;
    const int lkg0  = tid >> 7;
    const int tx = tid & 15, ty = tid >> 4;
    const int j0 = tx * 8,   r0 = ty * 8;

    const int rA = mBase + lrow;
    const int bA = rA >> 10, iA = rA & 1023;
    const float* Aptr = (iA > 0)
        ? out + ((size_t)bA * 2048 + 2 * iA - 1) * 256
        : hidden + (size_t)bA * 256;
    const float* Bptr = W + (size_t)(nBase + lrow) * 512 + 256;

    u64 acc[4][8];
    #pragma unroll
    for (int ri = 0; ri < 4; ri++)
        #pragma unroll
        for (int j = 0; j < 8; j++) acc[ri][j] = 0ull;

    gemm_mainloop(As, Bs, Aptr, Bptr, lrow, lkg0, r0, j0, acc);

    #pragma unroll
    for (int ri = 0; ri < 4; ri++) {
        #pragma unroll
        for (int half = 0; half < 2; half++) {
            const int rr = mBase + r0 + 2 * ri + half;
            const int b = rr >> 10, i = rr & 1023;
            float* orow = out + ((size_t)b * 2048 + 2 * i) * 256 + nBase + j0;
            float4 x0 = *(const float4*)(orow);
            float4 x1 = *(const float4*)(orow + 4);
            float v[8];
            #pragma unroll
            for (int j = 0; j < 8; j++) {
                float2 f = unpack2(acc[ri][j]);
                v[j] = half ? f.y : f.x;
            }
            *(float4*)(orow)     = make_float4(v[0]+x0.x, v[1]+x0.y, v[2]+x0.z, v[3]+x0.w);
            *(float4*)(orow + 4) = make_float4(v[4]+x1.x, v[5]+x1.y, v[6]+x1.z, v[7]+x1.w);
        }
    }
}

// =============================================================================
// Phase 2: W^2 scan, 1024 steps.  One CTA per batch, 512 threads.
//   s_i = W2 @ s_{i-1} + c_i,   s_{-1} = hidden,  s_i written to out[b, 2i+1, :]
// (c_i staged in out odd rows by corr_gemm; read-then-overwrite in place.)
// Weights (W2 row stride 256): 11 reg pairs + 5 SMEM pairs per (output, chunk).
// =============================================================================
__global__ __launch_bounds__(512, 1) void rnn_scan(
    const float* __restrict__ hidden, float* __restrict__ out)
{
    extern __shared__ u64 dynsm[];
    u64*   resw = dynsm;                     // [20][512] u64         (81920 B)
    float* part = (float*)(dynsm + 10240);   // [256*9] floats         (9216 B)
    u64*   h2   = dynsm + 11392;             // [2][8*17] u64 (padded) (2176 B)

    const int tid  = threadIdx.x;
    const int b    = blockIdx.x;
    const int q    = tid & 7;
    const int jset = tid >> 3;

    // ---- load W2 weights: 11 reg pairs + 5 residual pairs per (output, chunk) ----
    u64 w[4][11];
    #pragma unroll
    for (int u = 0; u < 4; u++) {
        const u64* wr = (const u64*)(g_W2 + (size_t)(jset * 4 + u) * 256);
        #pragma unroll
        for (int i = 0; i < 11; i++) w[u][i] = wr[q * 16 + i];
        #pragma unroll
        for (int ir = 0; ir < 5; ir++)
            resw[(u * 5 + ir) * 512 + tid] = wr[q * 16 + 11 + ir];
    }

    // ---- init s_{-1} = hidden ----
    if (tid < 128) {
        u64 hv = ((const u64*)(hidden + (size_t)b * 256))[tid];
        h2[(tid >> 4) * 17 + (tid & 15)] = hv;
    }

    // ---- prefetch c_0 (staged in out row 1) ----
    float xpre = 0.f;
    float* outp = out + (size_t)b * 2048 * 256 + 256 + tid;   // row 2*0+1, elem tid
    if (tid < 256) xpre = *outp;

    __syncthreads();

    const u64* rw = resw + tid;

    #pragma unroll 1
    for (int t = 0; t < 1024; t++) {
        const u64* hb = h2 + (t & 1) * 136 + q * 17;
        u64 a0 = 0, a1 = 0, a2 = 0, a3 = 0;
        #pragma unroll
        for (int i = 0; i < 11; i++) {
            u64 hh = hb[i];
            a0 = ffma2(w[0][i], hh, a0);
            a1 = ffma2(w[1][i], hh, a1);
            a2 = ffma2(w[2][i], hh, a2);
            a3 = ffma2(w[3][i], hh, a3);
        }
        #pragma unroll
        for (int ir = 0; ir < 5; ir++) {
            u64 hh = hb[11 + ir];
            a0 = ffma2(rw[(0 * 5 + ir) * 512], hh, a0);
            a1 = ffma2(rw[(1 * 5 + ir) * 512], hh, a1);
            a2 = ffma2(rw[(2 * 5 + ir) * 512], hh, a2);
            a3 = ffma2(rw[(3 * 5 + ir) * 512], hh, a3);
        }
        float2 f0 = unpack2(a0), f1 = unpack2(a1), f2 = unpack2(a2), f3 = unpack2(a3);
        const int pb = (jset * 4) * 9 + q;
        part[pb]      = f0.x + f0.y;
        part[pb + 9]  = f1.x + f1.y;
        part[pb + 18] = f2.x + f2.y;
        part[pb + 27] = f3.x + f3.y;
        __syncthreads();
        if (tid < 256) {
            const float* pr = part + tid * 9;
            float s = ((pr[0] + pr[1]) + (pr[2] + pr[3]))
                    + ((pr[4] + pr[5]) + (pr[6] + pr[7]));
            float hnew = s + xpre;
            int p = tid >> 1;
            float* hw = (float*)(h2 + ((t + 1) & 1) * 136);
            hw[((p >> 4) * 17 + (p & 15)) * 2 + (tid & 1)] = hnew;
            *outp = hnew;                       // h_{2t+1}
            if (t < 1023) xpre = outp[512];     // prefetch c_{t+1}
            outp += 512;
        }
        __syncthreads();
    }
}

// =============================================================================
extern "C" void kernel_launch(void* const* d_in, const int* in_sizes, int n_in,
                              void* d_out, int out_size)
{
    (void)in_sizes; (void)n_in; (void)out_size;
    const float* X      = (const float*)d_in[0];   // input_seq [64,2048,256]
    const float* hidden = (const float*)d_in[1];   // [64,256]
    const float* W      = (const float*)d_in[2];   // [256,512]
    const float* bias   = (const float*)d_in[3];   // [256]
    float* out          = (float*)d_out;           // [64,2048,256]

    // 1) xproj into d_out (in place).
    dim3 g1(1024, 2);
    xproj_gemm<<<g1, 256>>>(X, W, bias, out);

    // 2) W2 = Wh @ Wh.
    w2_kernel<<<256, 256>>>(W);

    // 3) corrections c_i = Wh @ xp_even + xp_odd  -> odd rows of out.
    dim3 g2(512, 2);
    corr_gemm<<<g2, 256>>>(W, out);

    // 4) W^2 scan, 1024 steps -> odd rows become h_odd.
    cudaFuncSetAttribute(rnn_scan, cudaFuncAttributeMaxDynamicSharedMemorySize, 93312);
    rnn_scan<<<64, 512, 93312>>>(hidden, out);

    // 5) backfill even rows: h_even = Wh @ h_odd_prev + xp_even.
    backfill_gemm<<<g2, 256>>>(W, hidden, out);
}

// round 9
// speedup vs baseline: 1.8307x; 1.1149x over previous
#include <cuda_runtime.h>
#include <cstdint>

typedef unsigned long long u64;

// fp32 scratch for W_h^2 and W_h^4  (device-global: allocation-free scratch)
__device__ float g_W2[256 * 256];
__device__ float g_W4[256 * 256];

// ---------------- f32x2 packed-fp32 helpers (Blackwell FFMA2 path) -----------
__device__ __forceinline__ u64 ffma2(u64 a, u64 b, u64 c) {
    u64 d;
    asm("fma.rn.f32x2 %0, %1, %2, %3;" : "=l"(d) : "l"(a), "l"(b), "l"(c));
    return d;
}
__device__ __forceinline__ u64 pack2(float lo, float hi) {
    u64 r;
    asm("mov.b64 %0, {%1, %2};" : "=l"(r) : "f"(lo), "f"(hi));
    return r;
}
__device__ __forceinline__ float2 unpack2(u64 v) {
    float2 f;
    asm("mov.b64 {%0, %1}, %2;" : "=f"(f.x), "=f"(f.y) : "l"(v));
    return f;
}

// =============================================================================
// GEMM mainloop core (shared).  As/Bs double-buffered 16x128 tiles; 256 thr;
// 8x8 microtile.  Aptr/Bptr are per-lrow row pointers (K contiguous, 256 long).
// =============================================================================
__device__ __forceinline__ void gemm_mainloop(
    float As[2][16][128], float Bs[2][16][128],
    const float* Aptr, const float* Bptr,
    int lrow, int lkg0, int r0, int j0, u64 acc[4][8])
{
    {
        float4 av0 = *(const float4*)(Aptr + lkg0 * 4);
        float4 av1 = *(const float4*)(Aptr + (lkg0 + 2) * 4);
        float4 bv0 = *(const float4*)(Bptr + lkg0 * 4);
        float4 bv1 = *(const float4*)(Bptr + (lkg0 + 2) * 4);
        const int ka = lkg0 * 4, kb = (lkg0 + 2) * 4;
        As[0][ka+0][lrow] = av0.x; As[0][ka+1][lrow] = av0.y;
        As[0][ka+2][lrow] = av0.z; As[0][ka+3][lrow] = av0.w;
        As[0][kb+0][lrow] = av1.x; As[0][kb+1][lrow] = av1.y;
        As[0][kb+2][lrow] = av1.z; As[0][kb+3][lrow] = av1.w;
        Bs[0][ka+0][lrow] = bv0.x; Bs[0][ka+1][lrow] = bv0.y;
        Bs[0][ka+2][lrow] = bv0.z; Bs[0][ka+3][lrow] = bv0.w;
        Bs[0][kb+0][lrow] = bv1.x; Bs[0][kb+1][lrow] = bv1.y;
        Bs[0][kb+2][lrow] = bv1.z; Bs[0][kb+3][lrow] = bv1.w;
    }
    __syncthreads();

    #pragma unroll 1
    for (int kt = 0; kt < 16; kt++) {
        const int cur = kt & 1;
        float4 na0, na1, nb0, nb1;
        if (kt < 15) {
            const float* ap = Aptr + (kt + 1) * 16;
            const float* bp = Bptr + (kt + 1) * 16;
            na0 = *(const float4*)(ap + lkg0 * 4);
            na1 = *(const float4*)(ap + (lkg0 + 2) * 4);
            nb0 = *(const float4*)(bp + lkg0 * 4);
            nb1 = *(const float4*)(bp + (lkg0 + 2) * 4);
        }
        #pragma unroll
        for (int k = 0; k < 16; k++) {
            float4 a0 = *(const float4*)&As[cur][k][r0];
            float4 a1 = *(const float4*)&As[cur][k][r0 + 4];
            float4 b0 = *(const float4*)&Bs[cur][k][j0];
            float4 b1 = *(const float4*)&Bs[cur][k][j0 + 4];
            u64 aa[4];
            aa[0] = pack2(a0.x, a0.y); aa[1] = pack2(a0.z, a0.w);
            aa[2] = pack2(a1.x, a1.y); aa[3] = pack2(a1.z, a1.w);
            float bsv[8] = {b0.x, b0.y, b0.z, b0.w, b1.x, b1.y, b1.z, b1.w};
            #pragma unroll
            for (int j = 0; j < 8; j++) {
                u64 bb = pack2(bsv[j], bsv[j]);
                #pragma unroll
                for (int ri = 0; ri < 4; ri++)
                    acc[ri][j] = ffma2(aa[ri], bb, acc[ri][j]);
            }
        }
        if (kt < 15) {
            const int nxt = cur ^ 1;
            const int ka = lkg0 * 4, kb = (lkg0 + 2) * 4;
            As[nxt][ka+0][lrow] = na0.x; As[nxt][ka+1][lrow] = na0.y;
            As[nxt][ka+2][lrow] = na0.z; As[nxt][ka+3][lrow] = na0.w;
            As[nxt][kb+0][lrow] = na1.x; As[nxt][kb+1][lrow] = na1.y;
            As[nxt][kb+2][lrow] = na1.z; As[nxt][kb+3][lrow] = na1.w;
            Bs[nxt][ka+0][lrow] = nb0.x; Bs[nxt][ka+1][lrow] = nb0.y;
            Bs[nxt][ka+2][lrow] = nb0.z; Bs[nxt][ka+3][lrow] = nb0.w;
            Bs[nxt][kb+0][lrow] = nb1.x; Bs[nxt][kb+1][lrow] = nb1.y;
            Bs[nxt][kb+2][lrow] = nb1.z; Bs[nxt][kb+3][lrow] = nb1.w;
        }
        __syncthreads();
    }
}

// Epilogue helper: add acc to existing row contents (in-place accumulate rows).
__device__ __forceinline__ void epilogue_accum_rows(
    u64 acc[4][8], float* __restrict__ out,
    int mBase, int nBase, int r0, int j0,
    int rows_per_batch_log2, int pos_mul, int pos_add)
{
    #pragma unroll
    for (int ri = 0; ri < 4; ri++) {
        #pragma unroll
        for (int half = 0; half < 2; half++) {
            const int rr = mBase + r0 + 2 * ri + half;
            const int b = rr >> rows_per_batch_log2;
            const int i = rr & ((1 << rows_per_batch_log2) - 1);
            float* orow = out + ((size_t)b * 2048 + (size_t)i * pos_mul + pos_add) * 256
                        + nBase + j0;
            float4 x0 = *(const float4*)(orow);
            float4 x1 = *(const float4*)(orow + 4);
            float v[8];
            #pragma unroll
            for (int j = 0; j < 8; j++) {
                float2 f = unpack2(acc[ri][j]);
                v[j] = half ? f.y : f.x;
            }
            *(float4*)(orow)     = make_float4(v[0]+x0.x, v[1]+x0.y, v[2]+x0.z, v[3]+x0.w);
            *(float4*)(orow + 4) = make_float4(v[4]+x1.x, v[5]+x1.y, v[6]+x1.z, v[7]+x1.w);
        }
    }
}

// =============================================================================
// Phase 1: x_proj GEMM.  out[row, j] = bias[j] + sum_k X[row,k] * W_x[j,k]
// =============================================================================
__global__ __launch_bounds__(256, 2) void xproj_gemm(
    const float* __restrict__ X, const float* __restrict__ W,
    const float* __restrict__ bias, float* __restrict__ out)
{
    __shared__ float As[2][16][128];
    __shared__ float Bs[2][16][128];

    const int tid   = threadIdx.x;
    const int mBase = blockIdx.x * 128;
    const int nBase = blockIdx.y * 128;
    const int lrow  = tid & 127;
    const int lkg0  = tid >> 7;
    const int tx = tid & 15, ty = tid >> 4;
    const int j0 = tx * 8,   r0 = ty * 8;

    const float* Aptr = X + (size_t)(mBase + lrow) * 256;
    const float* Bptr = W + (size_t)(nBase + lrow) * 512;

    u64 acc[4][8];
    #pragma unroll
    for (int ri = 0; ri < 4; ri++)
        #pragma unroll
        for (int j = 0; j < 8; j++) acc[ri][j] = 0ull;

    gemm_mainloop(As, Bs, Aptr, Bptr, lrow, lkg0, r0, j0, acc);

    float bvv[8];
    *(float4*)&bvv[0] = *(const float4*)(bias + nBase + j0);
    *(float4*)&bvv[4] = *(const float4*)(bias + nBase + j0 + 4);
    #pragma unroll
    for (int ri = 0; ri < 4; ri++) {
        float lo[8], hi[8];
        #pragma unroll
        for (int j = 0; j < 8; j++) {
            float2 f = unpack2(acc[ri][j]);
            lo[j] = f.x + bvv[j];
            hi[j] = f.y + bvv[j];
        }
        float* orow0 = out + (size_t)(mBase + r0 + 2 * ri) * 256 + nBase + j0;
        float* orow1 = orow0 + 256;
        *(float4*)(orow0)     = make_float4(lo[0], lo[1], lo[2], lo[3]);
        *(float4*)(orow0 + 4) = make_float4(lo[4], lo[5], lo[6], lo[7]);
        *(float4*)(orow1)     = make_float4(hi[0], hi[1], hi[2], hi[3]);
        *(float4*)(orow1 + 4) = make_float4(hi[4], hi[5], hi[6], hi[7]);
    }
}

// =============================================================================
// Matrix power kernels: g_W2 = Wh @ Wh,  g_W4 = g_W2 @ g_W2.
// =============================================================================
__global__ __launch_bounds__(256) void w2_kernel(const float* __restrict__ W)
{
    __shared__ float rowj[256];
    const int j = blockIdx.x, k = threadIdx.x;
    rowj[k] = W[(size_t)j * 512 + 256 + k];
    __syncthreads();
    float acc = 0.f;
    #pragma unroll 8
    for (int m = 0; m < 256; m++)
        acc += rowj[m] * W[(size_t)m * 512 + 256 + k];
    g_W2[j * 256 + k] = acc;
}

__global__ __launch_bounds__(256) void w4_kernel()
{
    __shared__ float rowj[256];
    const int j = blockIdx.x, k = threadIdx.x;
    rowj[k] = g_W2[j * 256 + k];
    __syncthreads();
    float acc = 0.f;
    #pragma unroll 8
    for (int m = 0; m < 256; m++)
        acc += rowj[m] * g_W2[m * 256 + k];
    g_W4[j * 256 + k] = acc;
}

// =============================================================================
// Level-1 corrections: t odd:  out[b,2i+1] += Wh @ xp[b,2i]     (65536 rows)
// =============================================================================
__global__ __launch_bounds__(256, 2) void corr1_gemm(
    const float* __restrict__ W, float* __restrict__ out)
{
    __shared__ float As[2][16][128];
    __shared__ float Bs[2][16][128];

    const int tid   = threadIdx.x;
    const int mBase = blockIdx.x * 128;
    const int nBase = blockIdx.y * 128;
    const int lrow  = tid & 127;
    const int lkg0  = tid >> 7;
    const int tx = tid & 15, ty = tid >> 4;
    const int j0 = tx * 8,   r0 = ty * 8;

    const int rA = mBase + lrow;
    const int bA = rA >> 10, iA = rA & 1023;
    const float* Aptr = out + ((size_t)bA * 2048 + 2 * iA) * 256;
    const float* Bptr = W + (size_t)(nBase + lrow) * 512 + 256;

    u64 acc[4][8];
    #pragma unroll
    for (int ri = 0; ri < 4; ri++)
        #pragma unroll
        for (int j = 0; j < 8; j++) acc[ri][j] = 0ull;

    gemm_mainloop(As, Bs, Aptr, Bptr, lrow, lkg0, r0, j0, acc);
    epilogue_accum_rows(acc, out, mBase, nBase, r0, j0, 10, 2, 1);
}

// =============================================================================
// Level-2 corrections: out[b,4i+3] += W2 @ c1[b,4i+1]           (32768 rows)
// =============================================================================
__global__ __launch_bounds__(256, 2) void corr2_gemm(float* __restrict__ out)
{
    __shared__ float As[2][16][128];
    __shared__ float Bs[2][16][128];

    const int tid   = threadIdx.x;
    const int mBase = blockIdx.x * 128;
    const int nBase = blockIdx.y * 128;
    const int lrow  = tid & 127;
    const int lkg0  = tid >> 7;
    const int tx = tid & 15, ty = tid >> 4;
    const int j0 = tx * 8,   r0 = ty * 8;

    const int rA = mBase + lrow;
    const int bA = rA >> 9, iA = rA & 511;
    const float* Aptr = out + ((size_t)bA * 2048 + 4 * iA + 1) * 256;
    const float* Bptr = g_W2 + (size_t)(nBase + lrow) * 256;

    u64 acc[4][8];
    #pragma unroll
    for (int ri = 0; ri < 4; ri++)
        #pragma unroll
        for (int j = 0; j < 8; j++) acc[ri][j] = 0ull;

    gemm_mainloop(As, Bs, Aptr, Bptr, lrow, lkg0, r0, j0, acc);
    epilogue_accum_rows(acc, out, mBase, nBase, r0, j0, 9, 4, 3);
}

// =============================================================================
// Backfill level-1: out[b,4i+1] += W2 @ h[b,4i-1]  (h[-1]=hidden) (32768 rows)
// =============================================================================
__global__ __launch_bounds__(256, 2) void backfill1_gemm(
    const float* __restrict__ hidden, float* __restrict__ out)
{
    __shared__ float As[2][16][128];
    __shared__ float Bs[2][16][128];

    const int tid   = threadIdx.x;
    const int mBase = blockIdx.x * 128;
    const int nBase = blockIdx.y * 128;
    const int lrow  = tid & 127;
    const int lkg0  = tid >> 7;
    const int tx = tid & 15, ty = tid >> 4;
    const int j0 = tx * 8,   r0 = ty * 8;

    const int rA = mBase + lrow;
    const int bA = rA >> 9, iA = rA & 511;
    const float* Aptr = (iA > 0)
        ? out + ((size_t)bA * 2048 + 4 * iA - 1) * 256
        : hidden + (size_t)bA * 256;
    const float* Bptr = g_W2 + (size_t)(nBase + lrow) * 256;

    u64 acc[4][8];
    #pragma unroll
    for (int ri = 0; ri < 4; ri++)
        #pragma unroll
        for (int j = 0; j < 8; j++) acc[ri][j] = 0ull;

    gemm_mainloop(As, Bs, Aptr, Bptr, lrow, lkg0, r0, j0, acc);
    epilogue_accum_rows(acc, out, mBase, nBase, r0, j0, 9, 4, 1);
}

// =============================================================================
// Backfill level-0: out[b,2i] += Wh @ h[b,2i-1]  (h[-1]=hidden)  (65536 rows)
// =============================================================================
__global__ __launch_bounds__(256, 2) void backfill0_gemm(
    const float* __restrict__ W, const float* __restrict__ hidden,
    float* __restrict__ out)
{
    __shared__ float As[2][16][128];
    __shared__ float Bs[2][16][128];

    const int tid   = threadIdx.x;
    const int mBase = blockIdx.x * 128;
    const int nBase = blockIdx.y * 128;
    const int lrow  = tid & 127;
    const int lkg0  = tid >> 7;
    const int tx = tid & 15, ty = tid >> 4;
    const int j0 = tx * 8,   r0 = ty * 8;

    const int rA = mBase + lrow;
    const int bA = rA >> 10, iA = rA & 1023;
    const float* Aptr = (iA > 0)
        ? out + ((size_t)bA * 2048 + 2 * iA - 1) * 256
        : hidden + (size_t)bA * 256;
    const float* Bptr = W + (size_t)(nBase + lrow) * 512 + 256;

    u64 acc[4][8];
    #pragma unroll
    for (int ri = 0; ri < 4; ri++)
        #pragma unroll
        for (int j = 0; j < 8; j++) acc[ri][j] = 0ull;

    gemm_mainloop(As, Bs, Aptr, Bptr, lrow, lkg0, r0, j0, acc);
    epilogue_accum_rows(acc, out, mBase, nBase, r0, j0, 10, 2, 0);
}

// =============================================================================
// Phase 2: W^4 scan, 512 steps.  One CTA per batch, 512 threads.
//   h_{4t+3} = W4 @ h_{4t-1} + c2_{4t+3}   (c2 staged in out rows ≡3 mod 4)
// =============================================================================
__global__ __launch_bounds__(512, 1) void rnn_scan(
    const float* __restrict__ hidden, float* __restrict__ out)
{
    extern __shared__ u64 dynsm[];
    u64*   resw = dynsm;                     // [20][512] u64         (81920 B)
    float* part = (float*)(dynsm + 10240);   // [256*9] floats         (9216 B)
    u64*   h2   = dynsm + 11392;             // [2][8*17] u64 (padded) (2176 B)

    const int tid  = threadIdx.x;
    const int b    = blockIdx.x;
    const int q    = tid & 7;
    const int jset = tid >> 3;

    // ---- load W4 weights: 11 reg pairs + 5 residual pairs per (output, chunk) ----
    u64 w[4][11];
    #pragma unroll
    for (int u = 0; u < 4; u++) {
        const u64* wr = (const u64*)(g_W4 + (size_t)(jset * 4 + u) * 256);
        #pragma unroll
        for (int i = 0; i < 11; i++) w[u][i] = wr[q * 16 + i];
        #pragma unroll
        for (int ir = 0; ir < 5; ir++)
            resw[(u * 5 + ir) * 512 + tid] = wr[q * 16 + 11 + ir];
    }

    // ---- init h_{-1} = hidden ----
    if (tid < 128) {
        u64 hv = ((const u64*)(hidden + (size_t)b * 256))[tid];
        h2[(tid >> 4) * 17 + (tid & 15)] = hv;
    }

    // ---- prefetch c2_3 (out row 3) ----
    float xpre = 0.f;
    float* outp = out + (size_t)b * 2048 * 256 + 3 * 256 + tid;
    if (tid < 256) xpre = *outp;

    __syncthreads();

    const u64* rw = resw + tid;

    #pragma unroll 1
    for (int t = 0; t < 512; t++) {
        const u64* hb = h2 + (t & 1) * 136 + q * 17;
        u64 a0 = 0, a1 = 0, a2 = 0, a3 = 0;
        #pragma unroll
        for (int i = 0; i < 11; i++) {
            u64 hh = hb[i];
            a0 = ffma2(w[0][i], hh, a0);
            a1 = ffma2(w[1][i], hh, a1);
            a2 = ffma2(w[2][i], hh, a2);
            a3 = ffma2(w[3][i], hh, a3);
        }
        #pragma unroll
        for (int ir = 0; ir < 5; ir++) {
            u64 hh = hb[11 + ir];
            a0 = ffma2(rw[(0 * 5 + ir) * 512], hh, a0);
            a1 = ffma2(rw[(1 * 5 + ir) * 512], hh, a1);
            a2 = ffma2(rw[(2 * 5 + ir) * 512], hh, a2);
            a3 = ffma2(rw[(3 * 5 + ir) * 512], hh, a3);
        }
        float2 f0 = unpack2(a0), f1 = unpack2(a1), f2 = unpack2(a2), f3 = unpack2(a3);
        const int pb = (jset * 4) * 9 + q;
        part[pb]      = f0.x + f0.y;
        part[pb + 9]  = f1.x + f1.y;
        part[pb + 18] = f2.x + f2.y;
        part[pb + 27] = f3.x + f3.y;
        __syncthreads();
        if (tid < 256) {
            const float* pr = part + tid * 9;
            float s = ((pr[0] + pr[1]) + (pr[2] + pr[3]))
                    + ((pr[4] + pr[5]) + (pr[6] + pr[7]));
            float hnew = s + xpre;
            int p = tid >> 1;
            float* hw = (float*)(h2 + ((t + 1) & 1) * 136);
            hw[((p >> 4) * 17 + (p & 15)) * 2 + (tid & 1)] = hnew;
            *outp = hnew;                        // h_{4t+3}
            if (t < 511) xpre = outp[1024];      // prefetch c2_{4(t+1)+3}
            outp += 1024;
        }
        __syncthreads();
    }
}

// =============================================================================
extern "C" void kernel_launch(void* const* d_in, const int* in_sizes, int n_in,
                              void* d_out, int out_size)
{
    (void)in_sizes; (void)n_in; (void)out_size;
    const float* X      = (const float*)d_in[0];   // input_seq [64,2048,256]
    const float* hidden = (const float*)d_in[1];   // [64,256]
    const float* W      = (const float*)d_in[2];   // [256,512]
    const float* bias   = (const float*)d_in[3];   // [256]
    float* out          = (float*)d_out;           // [64,2048,256]

    // 1) xproj into d_out (in place).
    dim3 g1(1024, 2);
    xproj_gemm<<<g1, 256>>>(X, W, bias, out);

    // 2) Wh powers.
    w2_kernel<<<256, 256>>>(W);
    w4_kernel<<<256, 256>>>();

    // 3) corrections tree.
    dim3 g2(512, 2);
    corr1_gemm<<<g2, 256>>>(W, out);              // odd rows -> c1
    dim3 g3(256, 2);
    corr2_gemm<<<g3, 256>>>(out);                 // rows 4i+3 -> c2

    // 4) W^4 scan, 512 steps -> rows 4i+3 become h.
    cudaFuncSetAttribute(rnn_scan, cudaFuncAttributeMaxDynamicSharedMemorySize, 93312);
    rnn_scan<<<64, 512, 93312>>>(hidden, out);

    // 5) backfill: rows 4i+1, then even rows.
    backfill1_gemm<<<g3, 256>>>(hidden, out);
    backfill0_gemm<<<g2, 256>>>(W, hidden, out);
}

// round 10
// speedup vs baseline: 1.8967x; 1.0361x over previous
#include <cuda_runtime.h>
#include <cstdint>

typedef unsigned long long u64;

// fp32 scratch for W_h powers (device-global: allocation-free scratch)
__device__ float g_W2[256 * 256];
__device__ float g_W4[256 * 256];
__device__ float g_W8[256 * 256];
__device__ float g_W16[256 * 256];

// ---------------- f32x2 packed-fp32 helpers (Blackwell FFMA2 path) -----------
__device__ __forceinline__ u64 ffma2(u64 a, u64 b, u64 c) {
    u64 d;
    asm("fma.rn.f32x2 %0, %1, %2, %3;" : "=l"(d) : "l"(a), "l"(b), "l"(c));
    return d;
}
__device__ __forceinline__ u64 pack2(float lo, float hi) {
    u64 r;
    asm("mov.b64 %0, {%1, %2};" : "=l"(r) : "f"(lo), "f"(hi));
    return r;
}
__device__ __forceinline__ float2 unpack2(u64 v) {
    float2 f;
    asm("mov.b64 {%0, %1}, %2;" : "=f"(f.x), "=f"(f.y) : "l"(v));
    return f;
}

// =============================================================================
// GEMM mainloop core (shared).  As/Bs double-buffered 16x128 tiles; 256 thr;
// 8x8 microtile.  Aptr/Bptr are per-lrow row pointers (K contiguous, 256 long).
// =============================================================================
__device__ __forceinline__ void gemm_mainloop(
    float As[2][16][128], float Bs[2][16][128],
    const float* Aptr, const float* Bptr,
    int lrow, int lkg0, int r0, int j0, u64 acc[4][8])
{
    {
        float4 av0 = *(const float4*)(Aptr + lkg0 * 4);
        float4 av1 = *(const float4*)(Aptr + (lkg0 + 2) * 4);
        float4 bv0 = *(const float4*)(Bptr + lkg0 * 4);
        float4 bv1 = *(const float4*)(Bptr + (lkg0 + 2) * 4);
        const int ka = lkg0 * 4, kb = (lkg0 + 2) * 4;
        As[0][ka+0][lrow] = av0.x; As[0][ka+1][lrow] = av0.y;
        As[0][ka+2][lrow] = av0.z; As[0][ka+3][lrow] = av0.w;
        As[0][kb+0][lrow] = av1.x; As[0][kb+1][lrow] = av1.y;
        As[0][kb+2][lrow] = av1.z; As[0][kb+3][lrow] = av1.w;
        Bs[0][ka+0][lrow] = bv0.x; Bs[0][ka+1][lrow] = bv0.y;
        Bs[0][ka+2][lrow] = bv0.z; Bs[0][ka+3][lrow] = bv0.w;
        Bs[0][kb+0][lrow] = bv1.x; Bs[0][kb+1][lrow] = bv1.y;
        Bs[0][kb+2][lrow] = bv1.z; Bs[0][kb+3][lrow] = bv1.w;
    }
    __syncthreads();

    #pragma unroll 1
    for (int kt = 0; kt < 16; kt++) {
        const int cur = kt & 1;
        float4 na0, na1, nb0, nb1;
        if (kt < 15) {
            const float* ap = Aptr + (kt + 1) * 16;
            const float* bp = Bptr + (kt + 1) * 16;
            na0 = *(const float4*)(ap + lkg0 * 4);
            na1 = *(const float4*)(ap + (lkg0 + 2) * 4);
            nb0 = *(const float4*)(bp + lkg0 * 4);
            nb1 = *(const float4*)(bp + (lkg0 + 2) * 4);
        }
        #pragma unroll
        for (int k = 0; k < 16; k++) {
            float4 a0 = *(const float4*)&As[cur][k][r0];
            float4 a1 = *(const float4*)&As[cur][k][r0 + 4];
            float4 b0 = *(const float4*)&Bs[cur][k][j0];
            float4 b1 = *(const float4*)&Bs[cur][k][j0 + 4];
            u64 aa[4];
            aa[0] = pack2(a0.x, a0.y); aa[1] = pack2(a0.z, a0.w);
            aa[2] = pack2(a1.x, a1.y); aa[3] = pack2(a1.z, a1.w);
            float bsv[8] = {b0.x, b0.y, b0.z, b0.w, b1.x, b1.y, b1.z, b1.w};
            #pragma unroll
            for (int j = 0; j < 8; j++) {
                u64 bb = pack2(bsv[j], bsv[j]);
                #pragma unroll
                for (int ri = 0; ri < 4; ri++)
                    acc[ri][j] = ffma2(aa[ri], bb, acc[ri][j]);
            }
        }
        if (kt < 15) {
            const int nxt = cur ^ 1;
            const int ka = lkg0 * 4, kb = (lkg0 + 2) * 4;
            As[nxt][ka+0][lrow] = na0.x; As[nxt][ka+1][lrow] = na0.y;
            As[nxt][ka+2][lrow] = na0.z; As[nxt][ka+3][lrow] = na0.w;
            As[nxt][kb+0][lrow] = na1.x; As[nxt][kb+1][lrow] = na1.y;
            As[nxt][kb+2][lrow] = na1.z; As[nxt][kb+3][lrow] = na1.w;
            Bs[nxt][ka+0][lrow] = nb0.x; Bs[nxt][ka+1][lrow] = nb0.y;
            Bs[nxt][ka+2][lrow] = nb0.z; Bs[nxt][ka+3][lrow] = nb0.w;
            Bs[nxt][kb+0][lrow] = nb1.x; Bs[nxt][kb+1][lrow] = nb1.y;
            Bs[nxt][kb+2][lrow] = nb1.z; Bs[nxt][kb+3][lrow] = nb1.w;
        }
        __syncthreads();
    }
}

// =============================================================================
// Phase 1: x_proj GEMM.  out[row, j] = bias[j] + sum_k X[row,k] * W_x[j,k]
// =============================================================================
__global__ __launch_bounds__(256, 2) void xproj_gemm(
    const float* __restrict__ X, const float* __restrict__ W,
    const float* __restrict__ bias, float* __restrict__ out)
{
    __shared__ float As[2][16][128];
    __shared__ float Bs[2][16][128];

    const int tid   = threadIdx.x;
    const int mBase = blockIdx.x * 128;
    const int nBase = blockIdx.y * 128;
    const int lrow  = tid & 127;
    const int lkg0  = tid >> 7;
    const int tx = tid & 15, ty = tid >> 4;
    const int j0 = tx * 8,   r0 = ty * 8;

    const float* Aptr = X + (size_t)(mBase + lrow) * 256;
    const float* Bptr = W + (size_t)(nBase + lrow) * 512;

    u64 acc[4][8];
    #pragma unroll
    for (int ri = 0; ri < 4; ri++)
        #pragma unroll
        for (int j = 0; j < 8; j++) acc[ri][j] = 0ull;

    gemm_mainloop(As, Bs, Aptr, Bptr, lrow, lkg0, r0, j0, acc);

    float bvv[8];
    *(float4*)&bvv[0] = *(const float4*)(bias + nBase + j0);
    *(float4*)&bvv[4] = *(const float4*)(bias + nBase + j0 + 4);
    #pragma unroll
    for (int ri = 0; ri < 4; ri++) {
        float lo[8], hi[8];
        #pragma unroll
        for (int j = 0; j < 8; j++) {
            float2 f = unpack2(acc[ri][j]);
            lo[j] = f.x + bvv[j];
            hi[j] = f.y + bvv[j];
        }
        float* orow0 = out + (size_t)(mBase + r0 + 2 * ri) * 256 + nBase + j0;
        float* orow1 = orow0 + 256;
        *(float4*)(orow0)     = make_float4(lo[0], lo[1], lo[2], lo[3]);
        *(float4*)(orow0 + 4) = make_float4(lo[4], lo[5], lo[6], lo[7]);
        *(float4*)(orow1)     = make_float4(hi[0], hi[1], hi[2], hi[3]);
        *(float4*)(orow1 + 4) = make_float4(hi[4], hi[5], hi[6], hi[7]);
    }
}

// =============================================================================
// Matrix power kernels: g_W2 = Wh @ Wh, then repeated squaring W4/W8/W16.
// =============================================================================
__global__ __launch_bounds__(256) void w2_kernel(const float* __restrict__ W)
{
    __shared__ float rowj[256];
    const int j = blockIdx.x, k = threadIdx.x;
    rowj[k] = W[(size_t)j * 512 + 256 + k];
    __syncthreads();
    float acc = 0.f;
    #pragma unroll 8
    for (int m = 0; m < 256; m++)
        acc += rowj[m] * W[(size_t)m * 512 + 256 + k];
    g_W2[j * 256 + k] = acc;
}

__global__ __launch_bounds__(256) void wsq_kernel(int which)
{
    const float* src = (which == 0) ? g_W2 : (which == 1) ? g_W4 : g_W8;
    float*       dst = (which == 0) ? g_W4 : (which == 1) ? g_W8 : g_W16;
    __shared__ float rowj[256];
    const int j = blockIdx.x, k = threadIdx.x;
    rowj[k] = src[j * 256 + k];
    __syncthreads();
    float acc = 0.f;
    #pragma unroll 8
    for (int m = 0; m < 256; m++)
        acc += rowj[m] * src[m * 256 + k];
    dst[j * 256 + k] = acc;
}

// =============================================================================
// Correction level j (1..4): rows t ≡ 2^j-1 (mod 2^j):
//   x_t += W^(2^(j-1)) @ x_{t - 2^(j-1)}        (in place in out)
// =============================================================================
__global__ __launch_bounds__(256, 2) void corr_gemm(
    const float* __restrict__ W, float* __restrict__ out, int level)
{
    __shared__ float As[2][16][128];
    __shared__ float Bs[2][16][128];

    const int tid   = threadIdx.x;
    const int mBase = blockIdx.x * 128;
    const int nBase = blockIdx.y * 128;
    const int lrow  = tid & 127;
    const int lkg0  = tid >> 7;
    const int tx = tid & 15, ty = tid >> 4;
    const int j0 = tx * 8,   r0 = ty * 8;

    const int log2rb = 11 - level;                 // rows per batch = 2^log2rb
    const int mask   = (1 << log2rb) - 1;
    const int rA = mBase + lrow;
    const int bA = rA >> log2rb, iA = rA & mask;
    const int tRow = (iA << level) + (1 << level) - 1;
    const int sRow = tRow - (1 << (level - 1));
    const float* Aptr = out + ((size_t)bA * 2048 + sRow) * 256;

    const float* Bmat; int bstr;
    if (level == 1)      { Bmat = W + 256; bstr = 512; }
    else if (level == 2) { Bmat = g_W2;    bstr = 256; }
    else if (level == 3) { Bmat = g_W4;    bstr = 256; }
    else                 { Bmat = g_W8;    bstr = 256; }
    const float* Bptr = Bmat + (size_t)(nBase + lrow) * bstr;

    u64 acc[4][8];
    #pragma unroll
    for (int ri = 0; ri < 4; ri++)
        #pragma unroll
        for (int j = 0; j < 8; j++) acc[ri][j] = 0ull;

    gemm_mainloop(As, Bs, Aptr, Bptr, lrow, lkg0, r0, j0, acc);

    #pragma unroll
    for (int ri = 0; ri < 4; ri++) {
        #pragma unroll
        for (int half = 0; half < 2; half++) {
            const int rr = mBase + r0 + 2 * ri + half;
            const int b = rr >> log2rb, i = rr & mask;
            const int t = (i << level) + (1 << level) - 1;
            float* orow = out + ((size_t)b * 2048 + t) * 256 + nBase + j0;
            float4 x0 = *(const float4*)(orow);
            float4 x1 = *(const float4*)(orow + 4);
            float v[8];
            #pragma unroll
            for (int j = 0; j < 8; j++) {
                float2 f = unpack2(acc[ri][j]);
                v[j] = half ? f.y : f.x;
            }
            *(float4*)(orow)     = make_float4(v[0]+x0.x, v[1]+x0.y, v[2]+x0.z, v[3]+x0.w);
            *(float4*)(orow + 4) = make_float4(v[4]+x1.x, v[5]+x1.y, v[6]+x1.z, v[7]+x1.w);
        }
    }
}

// =============================================================================
// Backfill level j (3..0): rows t ≡ 2^j-1 (mod 2^(j+1)):
//   h_t = W^(2^j) @ h_{t - 2^j} + x_t     (x_t = level-j corrected value)
//   (t - 2^j == -1  ->  hidden)
// =============================================================================
__global__ __launch_bounds__(256, 2) void backfill_gemm(
    const float* __restrict__ W, const float* __restrict__ hidden,
    float* __restrict__ out, int lev)
{
    __shared__ float As[2][16][128];
    __shared__ float Bs[2][16][128];

    const int tid   = threadIdx.x;
    const int mBase = blockIdx.x * 128;
    const int nBase = blockIdx.y * 128;
    const int lrow  = tid & 127;
    const int lkg0  = tid >> 7;
    const int tx = tid & 15, ty = tid >> 4;
    const int j0 = tx * 8,   r0 = ty * 8;

    const int log2rb = 10 - lev;                   // rows per batch = 2^log2rb
    const int mask   = (1 << log2rb) - 1;
    const int rA = mBase + lrow;
    const int bA = rA >> log2rb, iA = rA & mask;
    const int tRow = (iA << (lev + 1)) + (1 << lev) - 1;
    const int sRow = tRow - (1 << lev);            // == -1 when iA == 0
    const float* Aptr = (iA > 0)
        ? out + ((size_t)bA * 2048 + sRow) * 256
        : hidden + (size_t)bA * 256;

    const float* Bmat; int bstr;
    if (lev == 0)      { Bmat = W + 256; bstr = 512; }
    else if (lev == 1) { Bmat = g_W2;    bstr = 256; }
    else if (lev == 2) { Bmat = g_W4;    bstr = 256; }
    else               { Bmat = g_W8;    bstr = 256; }
    const float* Bptr = Bmat + (size_t)(nBase + lrow) * bstr;

    u64 acc[4][8];
    #pragma unroll
    for (int ri = 0; ri < 4; ri++)
        #pragma unroll
        for (int j = 0; j < 8; j++) acc[ri][j] = 0ull;

    gemm_mainloop(As, Bs, Aptr, Bptr, lrow, lkg0, r0, j0, acc);

    #pragma unroll
    for (int ri = 0; ri < 4; ri++) {
        #pragma unroll
        for (int half = 0; half < 2; half++) {
            const int rr = mBase + r0 + 2 * ri + half;
            const int b = rr >> log2rb, i = rr & mask;
            const int t = (i << (lev + 1)) + (1 << lev) - 1;
            float* orow = out + ((size_t)b * 2048 + t) * 256 + nBase + j0;
            float4 x0 = *(const float4*)(orow);
            float4 x1 = *(const float4*)(orow + 4);
            float v[8];
            #pragma unroll
            for (int j = 0; j < 8; j++) {
                float2 f = unpack2(acc[ri][j]);
                v[j] = half ? f.y : f.x;
            }
            *(float4*)(orow)     = make_float4(v[0]+x0.x, v[1]+x0.y, v[2]+x0.z, v[3]+x0.w);
            *(float4*)(orow + 4) = make_float4(v[4]+x1.x, v[5]+x1.y, v[6]+x1.z, v[7]+x1.w);
        }
    }
}

// =============================================================================
// Phase 2: W^16 scan, 128 steps.  One CTA per batch, 512 threads.
//   h_{16t+15} = W16 @ h_{16t-1} + c_{16t+15}  (c staged in out rows ≡15 mod 16)
// =============================================================================
__global__ __launch_bounds__(512, 1) void rnn_scan(
    const float* __restrict__ hidden, float* __restrict__ out)
{
    extern __shared__ u64 dynsm[];
    u64*   resw = dynsm;                     // [20][512] u64         (81920 B)
    float* part = (float*)(dynsm + 10240);   // [256*9] floats         (9216 B)
    u64*   h2   = dynsm + 11392;             // [2][8*17] u64 (padded) (2176 B)

    const int tid  = threadIdx.x;
    const int b    = blockIdx.x;
    const int q    = tid & 7;
    const int jset = tid >> 3;

    // ---- load W16 weights: 11 reg pairs + 5 residual pairs per (output, chunk) ----
    u64 w[4][11];
    #pragma unroll
    for (int u = 0; u < 4; u++) {
        const u64* wr = (const u64*)(g_W16 + (size_t)(jset * 4 + u) * 256);
        #pragma unroll
        for (int i = 0; i < 11; i++) w[u][i] = wr[q * 16 + i];
        #pragma unroll
        for (int ir = 0; ir < 5; ir++)
            resw[(u * 5 + ir) * 512 + tid] = wr[q * 16 + 11 + ir];
    }

    // ---- init h_{-1} = hidden ----
    if (tid < 128) {
        u64 hv = ((const u64*)(hidden + (size_t)b * 256))[tid];
        h2[(tid >> 4) * 17 + (tid & 15)] = hv;
    }

    // ---- prefetch c_15 (out row 15) ----
    float xpre = 0.f;
    float* outp = out + (size_t)b * 2048 * 256 + 15 * 256 + tid;
    if (tid < 256) xpre = *outp;

    __syncthreads();

    const u64* rw = resw + tid;

    #pragma unroll 1
    for (int t = 0; t < 128; t++) {
        const u64* hb = h2 + (t & 1) * 136 + q * 17;
        u64 a0 = 0, a1 = 0, a2 = 0, a3 = 0;
        #pragma unroll
        for (int i = 0; i < 11; i++) {
            u64 hh = hb[i];
            a0 = ffma2(w[0][i], hh, a0);
            a1 = ffma2(w[1][i], hh, a1);
            a2 = ffma2(w[2][i], hh, a2);
            a3 = ffma2(w[3][i], hh, a3);
        }
        #pragma unroll
        for (int ir = 0; ir < 5; ir++) {
            u64 hh = hb[11 + ir];
            a0 = ffma2(rw[(0 * 5 + ir) * 512], hh, a0);
            a1 = ffma2(rw[(1 * 5 + ir) * 512], hh, a1);
            a2 = ffma2(rw[(2 * 5 + ir) * 512], hh, a2);
            a3 = ffma2(rw[(3 * 5 + ir) * 512], hh, a3);
        }
        float2 f0 = unpack2(a0), f1 = unpack2(a1), f2 = unpack2(a2), f3 = unpack2(a3);
        const int pb = (jset * 4) * 9 + q;
        part[pb]      = f0.x + f0.y;
        part[pb + 9]  = f1.x + f1.y;
        part[pb + 18] = f2.x + f2.y;
        part[pb + 27] = f3.x + f3.y;
        __syncthreads();
        if (tid < 256) {
            const float* pr = part + tid * 9;
            float s = ((pr[0] + pr[1]) + (pr[2] + pr[3]))
                    + ((pr[4] + pr[5]) + (pr[6] + pr[7]));
            float hnew = s + xpre;
            int p = tid >> 1;
            float* hw = (float*)(h2 + ((t + 1) & 1) * 136);
            hw[((p >> 4) * 17 + (p & 15)) * 2 + (tid & 1)] = hnew;
            *outp = hnew;                        // h_{16t+15}
            if (t < 127) xpre = outp[4096];      // prefetch c_{16(t+1)+15}
            outp += 4096;
        }
        __syncthreads();
    }
}

// =============================================================================
extern "C" void kernel_launch(void* const* d_in, const int* in_sizes, int n_in,
                              void* d_out, int out_size)
{
    (void)in_sizes; (void)n_in; (void)out_size;
    const float* X      = (const float*)d_in[0];   // input_seq [64,2048,256]
    const float* hidden = (const float*)d_in[1];   // [64,256]
    const float* W      = (const float*)d_in[2];   // [256,512]
    const float* bias   = (const float*)d_in[3];   // [256]
    float* out          = (float*)d_out;           // [64,2048,256]

    // 1) xproj into d_out (in place).
    dim3 g1(1024, 2);
    xproj_gemm<<<g1, 256>>>(X, W, bias, out);

    // 2) Wh powers: W2, W4, W8, W16.
    w2_kernel<<<256, 256>>>(W);
    wsq_kernel<<<256, 256>>>(0);
    wsq_kernel<<<256, 256>>>(1);
    wsq_kernel<<<256, 256>>>(2);

    // 3) correction tree, levels 1..4.
    corr_gemm<<<dim3(512, 2), 256>>>(W, out, 1);
    corr_gemm<<<dim3(256, 2), 256>>>(W, out, 2);
    corr_gemm<<<dim3(128, 2), 256>>>(W, out, 3);
    corr_gemm<<<dim3(64,  2), 256>>>(W, out, 4);

    // 4) W^16 scan, 128 steps -> rows 16i+15 become h.
    cudaFuncSetAttribute(rnn_scan, cudaFuncAttributeMaxDynamicSharedMemorySize, 93312);
    rnn_scan<<<64, 512, 93312>>>(hidden, out);

    // 5) backfill levels 3..0.
    backfill_gemm<<<dim3(64,  2), 256>>>(W, hidden, out, 3);
    backfill_gemm<<<dim3(128, 2), 256>>>(W, hidden, out, 2);
    backfill_gemm<<<dim3(256, 2), 256>>>(W, hidden, out, 1);
    backfill_gemm<<<dim3(512, 2), 256>>>(W, hidden, out, 0);
}